// round 15
// baseline (speedup 1.0000x reference)
#include <cuda_runtime.h>
#include <math.h>

#define NG   128
#define PN   256
#define EPG  1024
#define NN   (NG*PN)     // 32768
#define NE   (NG*EPG)    // 131072
#define DD   128
#define OUTD 10

// ---------------- device scratch ----------------
__device__ float g_h[NN*DD];
__device__ float g_Zp[NN*DD];             // xf@Wasb + biasz
__device__ float g_nm[8*NN];              // [(r*4+c)*NN + n]
__device__ float g_aggxf[NN*64];
__device__ float g_deg[NN];
__device__ float g_aggea[NN*16];
__device__ float g_bcxf[2*NG*4*64];       // 1024 x 64:  sum_n nm * xf
__device__ float g_denr[2*NG*4];          // raw nm sums (no eps)
__device__ float g_cx[2*NG*4*DD];         // cent_x, 1024 x 128
__device__ float g_ccraw[2*NG*4*DD];      // Wgraw @ cent_x (unnormalized)
__device__ float g_hp[3*2*NG*4*DD];       // hcent partials (3 x 1024 x 128)
__device__ unsigned int g_maxbits;
__device__ float g_Z[NN*DD];
// fused weights
__device__ float g_Wab[64*128];           // Wa@W_b2c
__device__ float g_Wasb[64*128];          // Wa@W_sb
__device__ float g_Wawbb[64*128];         // Wa@W_bb
__device__ float g_WaWbc[64*128];         // Wa@W_bc
__device__ float g_W3[16*128];            // We@W_bb
__device__ float g_biash[128];            // ba@W_b2c
__device__ float g_biasz[128];            // ba@W_sb
__device__ float g_babb[128];             // ba@W_bb
__device__ float g_baWbc[128];            // ba@W_bc
__device__ float g_Was[64*8];             // Wa@W_score
__device__ float g_bs[8];                 // ba@W_score

// ---------------- packed f32x2 helpers ----------------
typedef unsigned long long u64t;
__device__ __forceinline__ u64t pk2(float lo, float hi) {
    u64t r; asm("mov.b64 %0, {%1,%2};" : "=l"(r) : "f"(lo), "f"(hi)); return r;
}
__device__ __forceinline__ void upk2(u64t v, float& lo, float& hi) {
    asm("mov.b64 {%0,%1}, %2;" : "=f"(lo), "=f"(hi) : "l"(v));
}
__device__ __forceinline__ void fma2(u64t& d, u64t a, u64t b) {
    asm("fma.rn.f32x2 %0, %1, %2, %0;" : "+l"(d) : "l"(a), "l"(b));
}

// ---------------------------------------------------------------------------
// GEMM pass: 128 rows x 128 cols per block, 256 threads.
// ---------------------------------------------------------------------------
template<bool SC>
__device__ __forceinline__ void mma_pass2(const float* __restrict__ A, int K,
                                          const float* __restrict__ Ws,
                                          u64t* As, int row0, int tid,
                                          int tr, int tc2, u64t acc[8][4],
                                          float ascale) {
    float4 pre[2];
#pragma unroll
    for (int it = 0; it < 2; it++) {
        int idx = tid + it*256; int lr = idx >> 2, lc = (idx & 3) * 4;
        pre[it] = *(const float4*)(A + (size_t)(row0 + lr)*K + lc);
    }
    for (int k0 = 0; k0 < K; k0 += 16) {
        __syncthreads();
#pragma unroll
        for (int it = 0; it < 2; it++) {
            int idx = tid + it*256; int lr = idx >> 2, lc = (idx & 3) * 4;
            float4 v = pre[it];
            if (SC) { v.x *= ascale; v.y *= ascale; v.z *= ascale; v.w *= ascale; }
            As[lr*17 + lc + 0] = pk2(v.x, v.x);
            As[lr*17 + lc + 1] = pk2(v.y, v.y);
            As[lr*17 + lc + 2] = pk2(v.z, v.z);
            As[lr*17 + lc + 3] = pk2(v.w, v.w);
        }
        __syncthreads();
        if (k0 + 16 < K) {
#pragma unroll
            for (int it = 0; it < 2; it++) {
                int idx = tid + it*256; int lr = idx >> 2, lc = (idx & 3) * 4;
                pre[it] = *(const float4*)(A + (size_t)(row0 + lr)*K + k0 + 16 + lc);
            }
        }
#pragma unroll
        for (int kk = 0; kk < 16; kk++) {
            const float* wrow = Ws + (k0 + kk)*128;
            u64t wv[4];
#pragma unroll
            for (int jp = 0; jp < 4; jp++)
                wv[jp] = *(const u64t*)(wrow + tc2 + 32*jp);
            u64t ap[8];
#pragma unroll
            for (int i = 0; i < 8; i++)
                ap[i] = As[(tr + 16*i)*17 + kk];
#pragma unroll
            for (int i = 0; i < 8; i++)
#pragma unroll
                for (int jp = 0; jp < 4; jp++) fma2(acc[i][jp], ap[i], wv[jp]);
        }
    }
}

__device__ __forceinline__ void acc_store(u64t acc[8][4], float* __restrict__ out,
                                          int row0, int tr, int tc2, int relu_flag) {
#pragma unroll
    for (int i = 0; i < 8; i++) {
        int row = row0 + tr + 16*i;
#pragma unroll
        for (int jp = 0; jp < 4; jp++) {
            int cb = tc2 + 32*jp;
            float lo, hi; upk2(acc[i][jp], lo, hi);
            if (relu_flag) { lo = fmaxf(lo, 0.f); hi = fmaxf(hi, 0.f); }
            out[(size_t)row*128 + cb]     = lo;
            out[(size_t)row*128 + cb + 1] = hi;
        }
    }
}

__device__ __forceinline__ void gemm_body(
        const float* __restrict__ A1, const float* __restrict__ W1, int K1,
        const float* __restrict__ A2, const float* __restrict__ W2, int K2,
        const float* __restrict__ bias,
        const float* __restrict__ rowscale,
        const float* __restrict__ rowvec,
        const float* __restrict__ addC,
        int relu_flag, float* __restrict__ out,
        int blk, float* sm) {
    float* Ws1 = sm;
    float* Ws2 = Ws1 + K1*128;
    u64t*  As  = (u64t*)(Ws2 + K2*128);

    const int tid = threadIdx.x;
    const int tr = tid >> 4, tc2 = (tid & 15) * 2;
    const int row0 = blk * 128;

    for (int i = tid*4; i < K1*128; i += 1024) *(float4*)(Ws1+i) = *(const float4*)(W1+i);
    if (A2) for (int i = tid*4; i < K2*128; i += 1024) *(float4*)(Ws2+i) = *(const float4*)(W2+i);

    u64t acc[8][4];
#pragma unroll
    for (int i = 0; i < 8; i++)
#pragma unroll
        for (int j = 0; j < 4; j++) acc[i][j] = 0ull;

    mma_pass2<false>(A1, K1, Ws1, As, row0, tid, tr, tc2, acc, 1.f);
    if (A2) mma_pass2<false>(A2, K2, Ws2, As, row0, tid, tr, tc2, acc, 1.f);

#pragma unroll
    for (int i = 0; i < 8; i++) {
        int row = row0 + tr + 16*i;
        float rs = rowscale ? rowscale[row] : 0.f;
#pragma unroll
        for (int jp = 0; jp < 4; jp++) {
            int cb = tc2 + 32*jp;
            float lo, hi; upk2(acc[i][jp], lo, hi);
            if (bias)   { lo += bias[cb];        hi += bias[cb+1]; }
            if (rowvec) { lo += rs * rowvec[cb]; hi += rs * rowvec[cb+1]; }
            if (addC) {
                lo += addC[(size_t)row*128 + cb];
                hi += addC[(size_t)row*128 + cb + 1];
            }
            if (relu_flag) { lo = fmaxf(lo, 0.f); hi = fmaxf(hi, 0.f); }
            out[(size_t)row*128 + cb]     = lo;
            out[(size_t)row*128 + cb + 1] = hi;
        }
    }
}

// ---------------------------------------------------------------------------
// MEGA1: dual-output GEMM, 256 blocks (single wave).
//   h  = relu(xf @ Wab + biash)
//   Zp = xf @ Wasb + biasz
// One A staging path, two weight banks, two accumulation passes.
// ---------------------------------------------------------------------------
__global__ void __launch_bounds__(256, 2)
mega1(const float* __restrict__ x_feat) {
    extern __shared__ float sm[];
    float* Ws1 = sm;                 // 8192 floats
    float* Ws2 = Ws1 + 8192;         // 8192 floats
    u64t*  As  = (u64t*)(Ws2 + 8192);

    const int tid = threadIdx.x;
    const int tr = tid >> 4, tc2 = (tid & 15) * 2;
    const int row0 = blockIdx.x * 128;

    for (int i = tid*4; i < 8192; i += 1024) {
        *(float4*)(Ws1+i) = *(const float4*)(g_Wab+i);
        *(float4*)(Ws2+i) = *(const float4*)(g_Wasb+i);
    }

    u64t acc[8][4];
#pragma unroll
    for (int i = 0; i < 8; i++)
#pragma unroll
        for (int j = 0; j < 4; j++) acc[i][j] = 0ull;
    mma_pass2<false>(x_feat, 64, Ws1, As, row0, tid, tr, tc2, acc, 1.f);
#pragma unroll
    for (int i = 0; i < 8; i++) {
        int row = row0 + tr + 16*i;
#pragma unroll
        for (int jp = 0; jp < 4; jp++) {
            int cb = tc2 + 32*jp;
            float lo, hi; upk2(acc[i][jp], lo, hi);
            lo = fmaxf(lo + g_biash[cb], 0.f);
            hi = fmaxf(hi + g_biash[cb+1], 0.f);
            g_h[(size_t)row*128 + cb]     = lo;
            g_h[(size_t)row*128 + cb + 1] = hi;
        }
    }
    __syncthreads();
#pragma unroll
    for (int i = 0; i < 8; i++)
#pragma unroll
        for (int j = 0; j < 4; j++) acc[i][j] = 0ull;
    mma_pass2<false>(x_feat, 64, Ws2, As, row0, tid, tr, tc2, acc, 1.f);
#pragma unroll
    for (int i = 0; i < 8; i++) {
        int row = row0 + tr + 16*i;
#pragma unroll
        for (int jp = 0; jp < 4; jp++) {
            int cb = tc2 + 32*jp;
            float lo, hi; upk2(acc[i][jp], lo, hi);
            g_Zp[(size_t)row*128 + cb]     = lo + g_biasz[cb];
            g_Zp[(size_t)row*128 + cb + 1] = hi + g_biasz[cb+1];
        }
    }
}

// ---------------------------------------------------------------------------
// MEGA2: blocks 0-255 Z-GEMM (K=80, addC=Zp);
// blocks 256-279: hcent partial GEMMs (hb = t&7, p = t>>3):
//   p0: bcxf(K=64)@WaWbc + denr*baWbc ; p1: (ccraw/max)@Wcc ; p2: cx@Wsc.
// ---------------------------------------------------------------------------
__global__ void __launch_bounds__(256, 2)
mega2(const float* __restrict__ Wcc_, const float* __restrict__ Wsc) {
    extern __shared__ float sm[];
    int b = blockIdx.x;
    if (b < 256) {
        gemm_body(g_aggxf, g_Wawbb, 64, g_aggea, g_W3, 16,
                  nullptr, g_deg, g_babb, g_Zp, 0, g_Z, b, sm);
        return;
    }
    const int t = b - 256;                 // 0..23
    const int hb = t & 7, p = t >> 3;
    const int tid = threadIdx.x;
    const int tr = tid >> 4, tc2 = (tid & 15) * 2;

    if (p == 0) {
        gemm_body(g_bcxf, g_WaWbc, 64, nullptr, nullptr, 0,
                  nullptr, g_denr, g_baWbc, nullptr, 0, g_hp, hb, sm);
    } else {
        float* Ws = sm;
        u64t*  As = (u64t*)(sm + 128*128);
        const int row0 = hb * 128;
        const float* Wsel = (p == 1) ? Wcc_ : Wsc;
        const float* Asel = (p == 1) ? g_ccraw : g_cx;
        const float ascale = (p == 1)
            ? 1.f / (__uint_as_float(g_maxbits) + 1e-9f) : 1.f;
        for (int i = tid*4; i < 128*128; i += 1024)
            *(float4*)(Ws+i) = *(const float4*)(Wsel+i);
        u64t acc[8][4];
#pragma unroll
        for (int i = 0; i < 8; i++)
#pragma unroll
            for (int j = 0; j < 4; j++) acc[i][j] = 0ull;
        mma_pass2<true>(Asel, 128, Ws, As, row0, tid, tr, tc2, acc, ascale);
        acc_store(acc, g_hp + (size_t)p*131072, row0, tr, tc2, 0);
    }
}

// ---------------------------------------------------------------------------
// Parallel weight precompute + counters reset.  grid = 277 x 128.
// ---------------------------------------------------------------------------
__global__ void prep_big(const float* __restrict__ Wa, const float* __restrict__ ba,
                         const float* __restrict__ Wb2c, const float* __restrict__ Wsb,
                         const float* __restrict__ Wbb, const float* __restrict__ We,
                         const float* __restrict__ Wbc, const float* __restrict__ Wscore) {
    int b = blockIdx.x, d = threadIdx.x;
    if (b < 64) {
        float a = 0.f;
        for (int k = 0; k < 128; k++) a = fmaf(Wa[b*128+k], Wb2c[k*128+d], a);
        g_Wab[b*128+d] = a;
    } else if (b < 128) {
        int f = b - 64; float a = 0.f;
        for (int k = 0; k < 128; k++) a = fmaf(Wa[f*128+k], Wsb[k*128+d], a);
        g_Wasb[f*128+d] = a;
    } else if (b < 144) {
        int q = b - 128; float a = 0.f;
        for (int k = 0; k < 128; k++) a = fmaf(We[q*128+k], Wbb[k*128+d], a);
        g_W3[q*128+d] = a;
    } else if (b < 208) {
        int f = b - 144; float a = 0.f;
        for (int k = 0; k < 128; k++) a = fmaf(Wa[f*128+k], Wbb[k*128+d], a);
        g_Wawbb[f*128+d] = a;
    } else if (b < 272) {
        int f = b - 208; float a = 0.f;
        for (int k = 0; k < 128; k++) a = fmaf(Wa[f*128+k], Wbc[k*128+d], a);
        g_WaWbc[f*128+d] = a;
    } else if (b == 272) {
        float a = 0.f;
        for (int k = 0; k < 128; k++) a = fmaf(ba[k], Wb2c[k*128+d], a);
        g_biash[d] = a;
    } else if (b == 273) {
        float a = 0.f;
        for (int k = 0; k < 128; k++) a = fmaf(ba[k], Wsb[k*128+d], a);
        g_biasz[d] = a;
    } else if (b == 274) {
        float a = 0.f;
        for (int k = 0; k < 128; k++) a = fmaf(ba[k], Wbb[k*128+d], a);
        g_babb[d] = a;
        if (d == 0) g_maxbits = 0u;
    } else if (b == 275) {
        float a = 0.f;
        for (int k = 0; k < 128; k++) a = fmaf(ba[k], Wbc[k*128+d], a);
        g_baWbc[d] = a;
    } else {
        for (int o = d; o < 520; o += 128) {
            int r = o >> 3, q = o & 7;
            const float* L = (r < 64) ? (Wa + r*128) : ba;
            float a = 0.f;
            for (int k = 0; k < 128; k++) a = fmaf(L[k], Wscore[k*8+q], a);
            if (r < 64) g_Was[r*8+q] = a; else g_bs[q] = a;
        }
    }
}

// ---------------------------------------------------------------------------
// Per-graph fused kernel.  1 block / graph, 1024 threads.  (R14 verbatim)
// ---------------------------------------------------------------------------
__global__ void __launch_bounds__(1024)
graph_kernel(const float* __restrict__ xf,
             const float* __restrict__ edge_attr,
             const int* __restrict__ ei,
             const float* __restrict__ Wedge) {
    extern __shared__ float smf[];
    float* nm_sm    = smf;               // 2048
    float* srcw     = nm_sm + 2048;      // 2048
    float* ea_sm    = srcw + 2048;       // 16384
    float* wnum_c   = ea_sm + 16384;     // 8192
    float* numh_sm  = wnum_c + 8192;     // 1024
    float* red_sm   = numh_sm + 1024;    // 1024
    float* numea_sm = red_sm + 1024;     // 128
    float* was_sm   = numea_sm + 128;    // 520
    float* w_sm     = was_sm + 520;      // 24
    float* den_sm   = w_sm + 24;         // 8
    float* denr_sm  = den_sm + 8;        // 8
    int* sl    = (int*)(denr_sm + 8);    // 1024
    int* dl    = sl + 1024;              // 1024
    int* deg   = dl + 1024;              // 256
    int* off   = deg + 256;              // 257
    int* cur   = off + 257;              // 256
    int* csr   = cur + 256;              // 1024
    int* deg_s = csr + 1024;             // 256
    int* off_s = deg_s + 256;            // 257
    int* cur_s = off_s + 257;            // 256
    int* csr_s = cur_s + 256;            // 1024

    float* cx_sm = ea_sm;
    float* We_sm = wnum_c;

    const int g = blockIdx.x;
    const int tid = threadIdx.x;
    const int gb = g * PN;
    const int ge = g * EPG;

    for (int i = tid*4; i < PN*64; i += 4096)
        *(float4*)(ea_sm + i) = *(const float4*)(xf + (size_t)gb*64 + i);
    for (int i = tid; i < 512; i += 1024) was_sm[i] = g_Was[i];
    if (tid < 8) was_sm[512 + tid] = g_bs[tid];
    if (tid < PN) { deg[tid] = 0; deg_s[tid] = 0; }
    if (tid < 20) w_sm[tid] = 0.f;
    __syncthreads();
    {
        int node = tid >> 2, q = tid & 3;
        float s0 = was_sm[512 + q], s1 = was_sm[512 + q + 4];
        const float* xrow = ea_sm + node*64;
        for (int k = 0; k < 64; k++) {
            float a = xrow[k];
            s0 = fmaf(a, was_sm[k*8 + q], s0);
            s1 = fmaf(a, was_sm[k*8 + q + 4], s1);
        }
        wnum_c[node*8 + q]     = s0;
        wnum_c[node*8 + q + 4] = s1;
    }
    __syncthreads();
    if (tid < 512) {
        int node = tid >> 1, r = tid & 1;
        float v[4];
#pragma unroll
        for (int c = 0; c < 4; c++) v[c] = wnum_c[node*8 + c*2 + r];
        float m = fmaxf(fmaxf(v[0], v[1]), fmaxf(v[2], v[3]));
        float e[4], sum = 0.f;
#pragma unroll
        for (int c = 0; c < 4; c++) { e[c] = expf(v[c] - m); sum += e[c]; }
        float inv = 1.f / sum;
#pragma unroll
        for (int c = 0; c < 4; c++) {
            float nv = e[c] * inv;
            nm_sm[(r*4 + c)*256 + node] = nv;
            g_nm[(size_t)(r*4 + c)*NN + gb + node] = nv;
        }
    }
    __syncthreads();

    float wp[20];
    {
        const int e = tid;
        int s = ei[ge + e] - gb;
        int d = ei[NE + ge + e] - gb;
        sl[e] = s; dl[e] = d;
        atomicAdd(&deg[d], 1);
        atomicAdd(&deg_s[s], 1);
        const float4* earow = (const float4*)(edge_attr + (size_t)(ge + e)*16);
        float4 e0 = earow[0], e1 = earow[1], e2 = earow[2], e3 = earow[3];

        float ns[8], nd[8];
#pragma unroll
        for (int rc = 0; rc < 8; rc++) {
            ns[rc] = nm_sm[rc*256 + s];
            nd[rc] = nm_sm[rc*256 + d];
        }
        __syncthreads();
        float4* eadst = (float4*)(ea_sm + e*16);
        eadst[0] = e0; eadst[1] = e1; eadst[2] = e2; eadst[3] = e3;
#pragma unroll
        for (int rc = 0; rc < 8; rc++)
            wnum_c[e*8 + rc] = nd[rc]*nd[rc]*ns[rc];
#pragma unroll
        for (int r = 0; r < 2; r++) {
            int b = r*4, w0 = r*10;
            wp[w0+0] = ns[b+0]*nd[b+1];
            wp[w0+1] = ns[b+0]*nd[b+2];
            wp[w0+2] = ns[b+0]*nd[b+3];
            wp[w0+3] = ns[b+1]*nd[b+2];
            wp[w0+4] = ns[b+1]*nd[b+3];
            wp[w0+5] = ns[b+2]*nd[b+3];
#pragma unroll
            for (int c = 0; c < 4; c++) wp[w0+6+c] = ns[b+c]*nd[b+c];
        }
    }
#pragma unroll
    for (int p = 0; p < 20; p++)
        for (int o = 16; o > 0; o >>= 1)
            wp[p] += __shfl_down_sync(0xffffffffu, wp[p], o);
    if ((tid & 31) == 0)
#pragma unroll
        for (int p = 0; p < 20; p++) atomicAdd(&w_sm[p], wp[p]);
    __syncthreads();

    {
        const int eh = tid >> 7, rcb = (tid >> 4) & 7, qb = tid & 15;
        float nacc = 0.f;
        for (int el = eh*128; el < eh*128 + 128; el++)
            nacc = fmaf(wnum_c[el*8 + rcb], ea_sm[el*16 + qb], nacc);
        red_sm[tid] = nacc;
    }
    __syncthreads();
    if (tid < 256) {
        int rc = tid >> 5, lane = tid & 31;
        float s = 0.f;
        for (int n = lane; n < PN; n += 32) s += nm_sm[rc*256 + n];
        for (int o = 16; o > 0; o >>= 1) s += __shfl_down_sync(0xffffffffu, s, o);
        if (lane == 0) { denr_sm[rc] = s; den_sm[rc] = s + 1e-6f; }
    }
    if (tid >= 512 && tid < 640) {
        int t = tid - 512;
        float v = 0.f;
#pragma unroll
        for (int j = 0; j < 8; j++) v += red_sm[t + j*128];
        numea_sm[t] = v;
    }

    if (tid < 64) {
        int lane = tid & 31;
        int* dga = (tid < 32) ? deg : deg_s;
        int* ofa = (tid < 32) ? off : off_s;
        int run = 0;
        for (int seg = 0; seg < 8; seg++) {
            int dv = dga[seg*32 + lane];
            int v = dv;
#pragma unroll
            for (int o = 1; o < 32; o <<= 1) {
                int t = __shfl_up_sync(0xffffffffu, v, o);
                if (lane >= o) v += t;
            }
            ofa[seg*32 + lane] = run + v - dv;
            run += __shfl_sync(0xffffffffu, v, 31);
        }
        if (lane == 31) ofa[PN] = run;
    }
    __syncthreads();
    if (tid < PN) { cur[tid] = off[tid]; cur_s[tid] = off_s[tid]; }
    __syncthreads();
    {
        int pos = atomicAdd(&cur[dl[tid]], 1);
        csr[pos] = tid;
        int pos2 = atomicAdd(&cur_s[sl[tid]], 1);
        csr_s[pos2] = tid;
    }
    __syncthreads();

    if (tid < PN) g_deg[gb + tid] = (float)deg[tid];

    for (int i = tid; i < PN*8; i += 1024) {
        int s = i >> 3, rc = i & 7;
        float a = 0.f;
        int e0 = off_s[s], e1 = off_s[s + 1];
        for (int ii = e0; ii < e1; ii++)
            a += wnum_c[csr_s[ii]*8 + rc];
        srcw[rc*256 + s] = a;
    }

    for (int i = tid; i < PN*16; i += 1024) {
        int nl = i >> 4, q = i & 15;
        float a = 0.f;
        int e0 = off[nl], e1 = off[nl + 1];
        for (int ii = e0; ii < e1; ii++)
            a += ea_sm[csr[ii]*16 + q];
        g_aggea[(size_t)(gb + nl)*16 + q] = a;
    }
    __syncthreads();

    {
        const int d64 = tid & 63, grp = tid >> 6;
        float bl[8];
#pragma unroll
        for (int rc = 0; rc < 8; rc++) bl[rc] = 0.f;
        for (int nl = grp; nl < PN; nl += 16) {
            float xv = xf[(size_t)(gb + nl)*64 + d64];
#pragma unroll
            for (int rc = 0; rc < 8; rc++)
                bl[rc] = fmaf(nm_sm[rc*256 + nl], xv, bl[rc]);
            float a = 0.f;
            int e0 = off[nl], e1 = off[nl + 1];
            for (int ii = e0; ii < e1; ii++)
                a += xf[(size_t)(gb + sl[csr[ii]])*64 + d64];
            g_aggxf[(size_t)(gb + nl)*64 + d64] = a;
        }
#pragma unroll
        for (int rc = 0; rc < 8; rc++)
            ea_sm[grp*512 + rc*64 + d64] = bl[rc];
    }
    __syncthreads();
    if (tid < 512) {
        float s = 0.f;
#pragma unroll
        for (int j = 0; j < 16; j++) s += ea_sm[j*512 + tid];
        int rc = tid >> 6, q = tid & 63;
        int r = rc >> 2, ci = rc & 3;
        g_bcxf[((size_t)(r*NG + g)*4 + ci)*64 + q] = s;
    }
    if (tid < 8) {
        int r = tid >> 2, ci = tid & 3;
        g_denr[(size_t)(r*NG + g)*4 + ci] = denr_sm[tid];
    }
    __syncthreads();

    {
        const int d = tid & 127, grp8 = tid >> 7;
        float numa[8];
#pragma unroll
        for (int rc = 0; rc < 8; rc++) numa[rc] = 0.f;
        for (int nl = grp8; nl < PN; nl += 8) {
            float hv = g_h[(size_t)(gb + nl)*128 + d];
#pragma unroll
            for (int rc = 0; rc < 8; rc++)
                numa[rc] = fmaf(nm_sm[rc*256 + nl] + srcw[rc*256 + nl], hv, numa[rc]);
        }
#pragma unroll
        for (int rc = 0; rc < 8; rc++)
            ea_sm[grp8*1024 + rc*128 + d] = numa[rc];
    }
    __syncthreads();
    {
        float s = 0.f;
#pragma unroll
        for (int j = 0; j < 8; j++) s += ea_sm[j*1024 + tid];
        numh_sm[tid] = s;
    }
    __syncthreads();

    {
        const int rc = tid >> 7, dd = tid & 127;
        const int r = rc >> 2, ci = rc & 3;
        for (int i = tid; i < 2048; i += 1024) We_sm[i] = Wedge[i];
        __syncthreads();
        float v = numh_sm[rc*128 + dd];
#pragma unroll
        for (int q = 0; q < 16; q++)
            v = fmaf(numea_sm[rc*16 + q], We_sm[q*128 + dd], v);
        v /= den_sm[rc];
        cx_sm[rc*128 + dd] = v;
        g_cx[((size_t)(r*NG + g)*4 + ci)*128 + dd] = v;
        __syncthreads();
        const int pidx[4][4] = { {6,0,1,2}, {0,7,3,4}, {1,3,8,5}, {2,4,5,9} };
        float a = 0.f;
#pragma unroll
        for (int j = 0; j < 4; j++) {
            float w = w_sm[r*10 + pidx[ci][j]];
            if (ci == j) w *= 0.5f;
            a = fmaf(w, cx_sm[(r*4 + j)*128 + dd], a);
        }
        g_ccraw[((size_t)(r*NG + g)*4 + ci)*128 + dd] = a;
    }

    if (tid < 32) {
        const int pidx[4][4] = { {6,0,1,2}, {0,7,3,4}, {1,3,8,5}, {2,4,5,9} };
        int r = tid >> 4, idx = tid & 15;
        int i = idx >> 2, j = idx & 3;
        float v = w_sm[r*10 + pidx[i][j]];
        if (i == j) v *= 0.5f;
        float m = v;
        for (int o = 16; o > 0; o >>= 1)
            m = fmaxf(m, __shfl_down_sync(0xffffffffu, m, o));
        if (tid == 0) atomicMax(&g_maxbits, __float_as_uint(m));
    }
}

// ---------------------------------------------------------------------------
// Final fused: hcw = relu(hp0+hp1+hp2)@Wcb (in-block, per graph);
// node = mean_r relu(Z + Sum_c nm*hcw); pool; heads.  grid = NG, 1024 thr.
// ---------------------------------------------------------------------------
__global__ void __launch_bounds__(1024)
final_kernel(const float* __restrict__ Wcb,
             const float* __restrict__ W_inter,
             const float* __restrict__ b_inter,
             const float* __restrict__ W_out,
             const float* __restrict__ b_out,
             float* __restrict__ out) {
    extern __shared__ float sm[];
    float* Wcb_s = sm;             // 16384
    float* hc    = Wcb_s + 16384;  // 1024
    float* hcw   = hc + 1024;      // 1024
    float* nm_s  = hcw + 1024;     // 2048
    float* red   = nm_s + 2048;    // 1024
    float* gs    = red + 1024;     // 128
    float* emb   = gs + 128;       // 128

    int g = blockIdx.x, tid = threadIdx.x;

    for (int i = tid*4; i < 16384; i += 4096)
        *(float4*)(Wcb_s + i) = *(const float4*)(Wcb + i);
    {
        int rc = tid >> 7, k = tid & 127;
        int r = rc >> 2, c = rc & 3;
        size_t o = ((size_t)(r*NG + g)*4 + c)*128 + k;
        float v = g_hp[o] + g_hp[131072 + o] + g_hp[262144 + o];
        hc[tid] = fmaxf(v, 0.f);
    }
    for (int i = tid; i < 2048; i += 1024)
        nm_s[i] = g_nm[(size_t)(i >> 8)*NN + g*PN + (i & 255)];
    __syncthreads();

    {
        int rc = tid >> 7, d = tid & 127;
        float a = 0.f;
#pragma unroll 4
        for (int k = 0; k < 128; k++)
            a = fmaf(hc[rc*128 + k], Wcb_s[k*128 + d], a);
        hcw[tid] = a;
    }
    __syncthreads();

    int d = tid & 127, q8 = tid >> 7;
    float acc = 0.f;
#pragma unroll 8
    for (int nl = q8; nl < PN; nl += 8) {
        float z = g_Z[(size_t)(g*PN + nl)*128 + d];
        float y0 = 0.f, y1 = 0.f;
#pragma unroll
        for (int c = 0; c < 4; c++) {
            y0 = fmaf(nm_s[c*256 + nl],       hcw[c*128 + d],       y0);
            y1 = fmaf(nm_s[(4 + c)*256 + nl], hcw[512 + c*128 + d], y1);
        }
        acc += 0.5f * (fmaxf(z + y0, 0.f) + fmaxf(z + y1, 0.f));
    }
    red[tid] = acc;
    __syncthreads();
    if (tid < 128) {
        float s = 0.f;
#pragma unroll
        for (int j = 0; j < 8; j++) s += red[tid + j*128];
        gs[tid] = s * (1.0f / PN);
    }
    __syncthreads();
    if (tid < 128) {
        float e = b_inter[tid];
        for (int k = 0; k < 128; k++) e = fmaf(gs[k], W_inter[k*128 + tid], e);
        emb[tid] = e;
    }
    __syncthreads();
    if (tid < OUTD) {
        float o = b_out[tid];
        for (int k = 0; k < 128; k++) o = fmaf(emb[k], W_out[k*OUTD + tid], o);
        out[g*OUTD + tid] = o;
    }
}

// ---------------------------------------------------------------------------
extern "C" void kernel_launch(void* const* d_in, const int* in_sizes, int n_in,
                              void* d_out, int out_size) {
    const float* x_feat    = (const float*)d_in[0];
    const float* edge_attr = (const float*)d_in[1];
    const float* W_atom    = (const float*)d_in[2];
    const float* b_atom    = (const float*)d_in[3];
    const float* W_score   = (const float*)d_in[4];
    const float* W_edge    = (const float*)d_in[5];
    const float* W_b2c     = (const float*)d_in[6];
    const float* W_bb      = (const float*)d_in[7];
    const float* W_bc      = (const float*)d_in[8];
    const float* W_cb      = (const float*)d_in[9];
    const float* W_cc      = (const float*)d_in[10];
    const float* W_sb      = (const float*)d_in[11];
    const float* W_sc      = (const float*)d_in[12];
    const float* W_inter   = (const float*)d_in[13];
    const float* b_inter   = (const float*)d_in[14];
    const float* W_out     = (const float*)d_in[15];
    const float* b_out     = (const float*)d_in[16];
    const int*   edge_index= (const int*)d_in[17];
    float* out = (float*)d_out;

    cudaFuncSetAttribute(mega1, cudaFuncAttributeMaxDynamicSharedMemorySize, 85000);
    cudaFuncSetAttribute(mega2, cudaFuncAttributeMaxDynamicSharedMemorySize, 85000);
    cudaFuncSetAttribute(graph_kernel, cudaFuncAttributeMaxDynamicSharedMemorySize, 152000);
    cudaFuncSetAttribute(final_kernel, cudaFuncAttributeMaxDynamicSharedMemorySize, 90000);

    const size_t smA = 128*17*8;   // packed u64 A tile = 17408

    // 1. fused weights + counter reset
    prep_big<<<277, 128>>>(W_atom, b_atom, W_b2c, W_sb, W_bb, W_edge, W_bc, W_score);
    // 2. dual-output GEMM: h + Zp (single wave)
    mega1<<<256, 256, 2*8192*4 + smA>>>(x_feat);
    // 3. per-graph fused pass
    graph_kernel<<<NG, 1024, 148200>>>(x_feat, edge_attr, edge_index, W_edge);
    // 4. Z-GEMM (K=80, +Zp) + hcent partials in one launch (280 blocks)
    mega2<<<280, 256, 128*128*4 + smA>>>(W_cc, W_sc);
    // 5. fused hcw + Y + relu + mean + pool + heads
    final_kernel<<<NG, 1024, 88000>>>(W_cb, W_inter, b_inter, W_out, b_out, out);
}

// round 16
// speedup vs baseline: 1.0733x; 1.0733x over previous
#include <cuda_runtime.h>
#include <math.h>

#define NG   128
#define PN   256
#define EPG  1024
#define NN   (NG*PN)     // 32768
#define NE   (NG*EPG)    // 131072
#define DD   128
#define OUTD 10
#define ASTRIDE 2176     // 128*17 u64 per A buffer

// ---------------- device scratch ----------------
__device__ float g_h[NN*DD];
__device__ float g_nm[8*NN];              // [(r*4+c)*NN + n]
__device__ float g_aggxf[NN*64];
__device__ float g_deg[NN];
__device__ float g_aggea[NN*16];
__device__ float g_bcxf[2*NG*4*64];       // 1024 x 64:  sum_n nm * xf
__device__ float g_denr[2*NG*4];          // raw nm sums (no eps)
__device__ float g_cx[2*NG*4*DD];         // cent_x, 1024 x 128
__device__ float g_ccraw[2*NG*4*DD];      // Wgraw @ cent_x (unnormalized)
__device__ float g_hp[3*2*NG*4*DD];       // hcent partials (3 x 1024 x 128)
__device__ unsigned int g_maxbits;
__device__ float g_Z[NN*DD];
// fused weights
__device__ float g_Wab[64*128];           // Wa@W_b2c
__device__ float g_Wasb[64*128];          // Wa@W_sb
__device__ float g_Wawbb[64*128];         // Wa@W_bb
__device__ float g_WaWbc[64*128];         // Wa@W_bc
__device__ float g_W3[16*128];            // We@W_bb
__device__ float g_biash[128];            // ba@W_b2c
__device__ float g_biasz[128];            // ba@W_sb
__device__ float g_babb[128];             // ba@W_bb
__device__ float g_baWbc[128];            // ba@W_bc
__device__ float g_Was[64*8];             // Wa@W_score
__device__ float g_bs[8];                 // ba@W_score

// ---------------- packed f32x2 helpers ----------------
typedef unsigned long long u64t;
__device__ __forceinline__ u64t pk2(float lo, float hi) {
    u64t r; asm("mov.b64 %0, {%1,%2};" : "=l"(r) : "f"(lo), "f"(hi)); return r;
}
__device__ __forceinline__ void upk2(u64t v, float& lo, float& hi) {
    asm("mov.b64 {%0,%1}, %2;" : "=f"(lo), "=f"(hi) : "l"(v));
}
__device__ __forceinline__ void fma2(u64t& d, u64t a, u64t b) {
    asm("fma.rn.f32x2 %0, %1, %2, %0;" : "+l"(d) : "l"(a), "l"(b));
}

// ---------------------------------------------------------------------------
// GEMM pass: 128 rows x 128 cols per block, 256 threads.
// Ping-pong double-buffered A staging: ONE barrier per 16-wide K chunk.
// As must hold 2*ASTRIDE u64.
// ---------------------------------------------------------------------------
template<bool SC>
__device__ __forceinline__ void mma_pass2(const float* __restrict__ A, int K,
                                          const float* __restrict__ Ws,
                                          u64t* As, int row0, int tid,
                                          int tr, int tc2, u64t acc[8][4],
                                          float ascale) {
    const int lrA = tid >> 2,          lcA = (tid & 3) * 4;
    const int lrB = (tid + 256) >> 2;  // lcB == lcA (256 % 4 == 0)

    // stage chunk 0 -> buffer 0
    {
        float4 v = *(const float4*)(A + (size_t)(row0 + lrA)*K + lcA);
        float4 w = *(const float4*)(A + (size_t)(row0 + lrB)*K + lcA);
        if (SC) { v.x*=ascale; v.y*=ascale; v.z*=ascale; v.w*=ascale;
                  w.x*=ascale; w.y*=ascale; w.z*=ascale; w.w*=ascale; }
        As[lrA*17 + lcA + 0] = pk2(v.x, v.x);
        As[lrA*17 + lcA + 1] = pk2(v.y, v.y);
        As[lrA*17 + lcA + 2] = pk2(v.z, v.z);
        As[lrA*17 + lcA + 3] = pk2(v.w, v.w);
        As[lrB*17 + lcA + 0] = pk2(w.x, w.x);
        As[lrB*17 + lcA + 1] = pk2(w.y, w.y);
        As[lrB*17 + lcA + 2] = pk2(w.z, w.z);
        As[lrB*17 + lcA + 3] = pk2(w.w, w.w);
    }
    __syncthreads();

    const int nch = K >> 4;
    for (int i = 0; i < nch; i++) {
        const u64t* cb = As + (i & 1) * ASTRIDE;
        u64t* nb = As + ((i + 1) & 1) * ASTRIDE;
        float4 v, w;
        const bool more = (i + 1 < nch);
        if (more) {
            v = *(const float4*)(A + (size_t)(row0 + lrA)*K + (i+1)*16 + lcA);
            w = *(const float4*)(A + (size_t)(row0 + lrB)*K + (i+1)*16 + lcA);
        }
#pragma unroll
        for (int kk = 0; kk < 16; kk++) {
            const float* wrow = Ws + (i*16 + kk)*128;
            u64t wv[4];
#pragma unroll
            for (int jp = 0; jp < 4; jp++)
                wv[jp] = *(const u64t*)(wrow + tc2 + 32*jp);
            u64t ap[8];
#pragma unroll
            for (int r = 0; r < 8; r++)
                ap[r] = cb[(tr + 16*r)*17 + kk];
#pragma unroll
            for (int r = 0; r < 8; r++)
#pragma unroll
                for (int jp = 0; jp < 4; jp++) fma2(acc[r][jp], ap[r], wv[jp]);
        }
        if (more) {
            if (SC) { v.x*=ascale; v.y*=ascale; v.z*=ascale; v.w*=ascale;
                      w.x*=ascale; w.y*=ascale; w.z*=ascale; w.w*=ascale; }
            nb[lrA*17 + lcA + 0] = pk2(v.x, v.x);
            nb[lrA*17 + lcA + 1] = pk2(v.y, v.y);
            nb[lrA*17 + lcA + 2] = pk2(v.z, v.z);
            nb[lrA*17 + lcA + 3] = pk2(v.w, v.w);
            nb[lrB*17 + lcA + 0] = pk2(w.x, w.x);
            nb[lrB*17 + lcA + 1] = pk2(w.y, w.y);
            nb[lrB*17 + lcA + 2] = pk2(w.z, w.z);
            nb[lrB*17 + lcA + 3] = pk2(w.w, w.w);
        }
        __syncthreads();
    }
}

__device__ __forceinline__ void acc_store(u64t acc[8][4], float* __restrict__ out,
                                          int row0, int tr, int tc2, int relu_flag) {
#pragma unroll
    for (int i = 0; i < 8; i++) {
        int row = row0 + tr + 16*i;
#pragma unroll
        for (int jp = 0; jp < 4; jp++) {
            int cb = tc2 + 32*jp;
            float lo, hi; upk2(acc[i][jp], lo, hi);
            if (relu_flag) { lo = fmaxf(lo, 0.f); hi = fmaxf(hi, 0.f); }
            out[(size_t)row*128 + cb]     = lo;
            out[(size_t)row*128 + cb + 1] = hi;
        }
    }
}

__device__ __forceinline__ void gemm_body(
        const float* __restrict__ A1, const float* __restrict__ W1, int K1,
        const float* __restrict__ A2, const float* __restrict__ W2, int K2,
        const float* __restrict__ A3, const float* __restrict__ W3, int K3,
        const float* __restrict__ bias,
        const float* __restrict__ rowscale,
        const float* __restrict__ rowvec,
        int relu_flag, float* __restrict__ out,
        int blk, float* sm) {
    float* Ws1 = sm;
    float* Ws2 = Ws1 + K1*128;
    float* Ws3 = Ws2 + K2*128;
    u64t*  As  = (u64t*)(Ws3 + K3*128);

    const int tid = threadIdx.x;
    const int tr = tid >> 4, tc2 = (tid & 15) * 2;
    const int row0 = blk * 128;

    for (int i = tid*4; i < K1*128; i += 1024) *(float4*)(Ws1+i) = *(const float4*)(W1+i);
    if (A2) for (int i = tid*4; i < K2*128; i += 1024) *(float4*)(Ws2+i) = *(const float4*)(W2+i);
    if (A3) for (int i = tid*4; i < K3*128; i += 1024) *(float4*)(Ws3+i) = *(const float4*)(W3+i);

    u64t acc[8][4];
#pragma unroll
    for (int i = 0; i < 8; i++)
#pragma unroll
        for (int j = 0; j < 4; j++) acc[i][j] = 0ull;

    mma_pass2<false>(A1, K1, Ws1, As, row0, tid, tr, tc2, acc, 1.f);
    if (A2) mma_pass2<false>(A2, K2, Ws2, As, row0, tid, tr, tc2, acc, 1.f);
    if (A3) mma_pass2<false>(A3, K3, Ws3, As, row0, tid, tr, tc2, acc, 1.f);

#pragma unroll
    for (int i = 0; i < 8; i++) {
        int row = row0 + tr + 16*i;
        float rs = rowscale ? rowscale[row] : 0.f;
#pragma unroll
        for (int jp = 0; jp < 4; jp++) {
            int cb = tc2 + 32*jp;
            float lo, hi; upk2(acc[i][jp], lo, hi);
            if (bias)   { lo += bias[cb];        hi += bias[cb+1]; }
            if (rowvec) { lo += rs * rowvec[cb]; hi += rs * rowvec[cb+1]; }
            if (relu_flag) { lo = fmaxf(lo, 0.f); hi = fmaxf(hi, 0.f); }
            out[(size_t)row*128 + cb]     = lo;
            out[(size_t)row*128 + cb + 1] = hi;
        }
    }
}

// ---------------------------------------------------------------------------
// MEGA1: pure h-GEMM, 256 blocks (single wave).
// ---------------------------------------------------------------------------
__global__ void __launch_bounds__(256, 2)
mega1(const float* __restrict__ x_feat) {
    extern __shared__ float sm[];
    gemm_body(x_feat, g_Wab, 64, nullptr, nullptr, 0, nullptr, nullptr, 0,
              g_biash, nullptr, nullptr, 1, g_h, blockIdx.x, sm);
}

// ---------------------------------------------------------------------------
// MEGA2: blocks 0-255 Z-GEMM (K=144);
// blocks 256-279: hcent partial GEMMs (hb = t&7, p = t>>3):
//   p0: bcxf(K=64)@WaWbc + denr*baWbc ; p1: (ccraw/max)@Wcc ; p2: cx@Wsc.
// ---------------------------------------------------------------------------
__global__ void __launch_bounds__(256, 2)
mega2(const float* __restrict__ x_feat,
      const float* __restrict__ Wcc_, const float* __restrict__ Wsc) {
    extern __shared__ float sm[];
    int b = blockIdx.x;
    if (b < 256) {
        gemm_body(g_aggxf, g_Wawbb, 64, x_feat, g_Wasb, 64, g_aggea, g_W3, 16,
                  g_biasz, g_deg, g_babb, 0, g_Z, b, sm);
        return;
    }
    const int t = b - 256;                 // 0..23
    const int hb = t & 7, p = t >> 3;
    const int tid = threadIdx.x;
    const int tr = tid >> 4, tc2 = (tid & 15) * 2;

    if (p == 0) {
        gemm_body(g_bcxf, g_WaWbc, 64, nullptr, nullptr, 0, nullptr, nullptr, 0,
                  nullptr, g_denr, g_baWbc, 0, g_hp, hb, sm);
    } else {
        float* Ws = sm;
        u64t*  As = (u64t*)(sm + 128*128);
        const int row0 = hb * 128;
        const float* Wsel = (p == 1) ? Wcc_ : Wsc;
        const float* Asel = (p == 1) ? g_ccraw : g_cx;
        const float ascale = (p == 1)
            ? 1.f / (__uint_as_float(g_maxbits) + 1e-9f) : 1.f;
        for (int i = tid*4; i < 128*128; i += 1024)
            *(float4*)(Ws+i) = *(const float4*)(Wsel+i);
        u64t acc[8][4];
#pragma unroll
        for (int i = 0; i < 8; i++)
#pragma unroll
            for (int j = 0; j < 4; j++) acc[i][j] = 0ull;
        mma_pass2<true>(Asel, 128, Ws, As, row0, tid, tr, tc2, acc, ascale);
        acc_store(acc, g_hp + (size_t)p*131072, row0, tr, tc2, 0);
    }
}

// ---------------------------------------------------------------------------
// Parallel weight precompute + counters reset.  grid = 277 x 128.
// ---------------------------------------------------------------------------
__global__ void prep_big(const float* __restrict__ Wa, const float* __restrict__ ba,
                         const float* __restrict__ Wb2c, const float* __restrict__ Wsb,
                         const float* __restrict__ Wbb, const float* __restrict__ We,
                         const float* __restrict__ Wbc, const float* __restrict__ Wscore) {
    int b = blockIdx.x, d = threadIdx.x;
    if (b < 64) {
        float a = 0.f;
        for (int k = 0; k < 128; k++) a = fmaf(Wa[b*128+k], Wb2c[k*128+d], a);
        g_Wab[b*128+d] = a;
    } else if (b < 128) {
        int f = b - 64; float a = 0.f;
        for (int k = 0; k < 128; k++) a = fmaf(Wa[f*128+k], Wsb[k*128+d], a);
        g_Wasb[f*128+d] = a;
    } else if (b < 144) {
        int q = b - 128; float a = 0.f;
        for (int k = 0; k < 128; k++) a = fmaf(We[q*128+k], Wbb[k*128+d], a);
        g_W3[q*128+d] = a;
    } else if (b < 208) {
        int f = b - 144; float a = 0.f;
        for (int k = 0; k < 128; k++) a = fmaf(Wa[f*128+k], Wbb[k*128+d], a);
        g_Wawbb[f*128+d] = a;
    } else if (b < 272) {
        int f = b - 208; float a = 0.f;
        for (int k = 0; k < 128; k++) a = fmaf(Wa[f*128+k], Wbc[k*128+d], a);
        g_WaWbc[f*128+d] = a;
    } else if (b == 272) {
        float a = 0.f;
        for (int k = 0; k < 128; k++) a = fmaf(ba[k], Wb2c[k*128+d], a);
        g_biash[d] = a;
    } else if (b == 273) {
        float a = 0.f;
        for (int k = 0; k < 128; k++) a = fmaf(ba[k], Wsb[k*128+d], a);
        g_biasz[d] = a;
    } else if (b == 274) {
        float a = 0.f;
        for (int k = 0; k < 128; k++) a = fmaf(ba[k], Wbb[k*128+d], a);
        g_babb[d] = a;
        if (d == 0) g_maxbits = 0u;
    } else if (b == 275) {
        float a = 0.f;
        for (int k = 0; k < 128; k++) a = fmaf(ba[k], Wbc[k*128+d], a);
        g_baWbc[d] = a;
    } else {
        for (int o = d; o < 520; o += 128) {
            int r = o >> 3, q = o & 7;
            const float* L = (r < 64) ? (Wa + r*128) : ba;
            float a = 0.f;
            for (int k = 0; k < 128; k++) a = fmaf(L[k], Wscore[k*8+q], a);
            if (r < 64) g_Was[r*8+q] = a; else g_bs[q] = a;
        }
    }
}

// ---------------------------------------------------------------------------
// Per-graph fused kernel.  1 block / graph, 1024 threads.  (R14 verbatim)
// ---------------------------------------------------------------------------
__global__ void __launch_bounds__(1024)
graph_kernel(const float* __restrict__ xf,
             const float* __restrict__ edge_attr,
             const int* __restrict__ ei,
             const float* __restrict__ Wedge) {
    extern __shared__ float smf[];
    float* nm_sm    = smf;               // 2048
    float* srcw     = nm_sm + 2048;      // 2048
    float* ea_sm    = srcw + 2048;       // 16384
    float* wnum_c   = ea_sm + 16384;     // 8192
    float* numh_sm  = wnum_c + 8192;     // 1024
    float* red_sm   = numh_sm + 1024;    // 1024
    float* numea_sm = red_sm + 1024;     // 128
    float* was_sm   = numea_sm + 128;    // 520
    float* w_sm     = was_sm + 520;      // 24
    float* den_sm   = w_sm + 24;         // 8
    float* denr_sm  = den_sm + 8;        // 8
    int* sl    = (int*)(denr_sm + 8);    // 1024
    int* dl    = sl + 1024;              // 1024
    int* deg   = dl + 1024;              // 256
    int* off   = deg + 256;              // 257
    int* cur   = off + 257;              // 256
    int* csr   = cur + 256;              // 1024
    int* deg_s = csr + 1024;             // 256
    int* off_s = deg_s + 256;            // 257
    int* cur_s = off_s + 257;            // 256
    int* csr_s = cur_s + 256;            // 1024

    float* cx_sm = ea_sm;
    float* We_sm = wnum_c;

    const int g = blockIdx.x;
    const int tid = threadIdx.x;
    const int gb = g * PN;
    const int ge = g * EPG;

    for (int i = tid*4; i < PN*64; i += 4096)
        *(float4*)(ea_sm + i) = *(const float4*)(xf + (size_t)gb*64 + i);
    for (int i = tid; i < 512; i += 1024) was_sm[i] = g_Was[i];
    if (tid < 8) was_sm[512 + tid] = g_bs[tid];
    if (tid < PN) { deg[tid] = 0; deg_s[tid] = 0; }
    if (tid < 20) w_sm[tid] = 0.f;
    __syncthreads();
    {
        int node = tid >> 2, q = tid & 3;
        float s0 = was_sm[512 + q], s1 = was_sm[512 + q + 4];
        const float* xrow = ea_sm + node*64;
        for (int k = 0; k < 64; k++) {
            float a = xrow[k];
            s0 = fmaf(a, was_sm[k*8 + q], s0);
            s1 = fmaf(a, was_sm[k*8 + q + 4], s1);
        }
        wnum_c[node*8 + q]     = s0;
        wnum_c[node*8 + q + 4] = s1;
    }
    __syncthreads();
    if (tid < 512) {
        int node = tid >> 1, r = tid & 1;
        float v[4];
#pragma unroll
        for (int c = 0; c < 4; c++) v[c] = wnum_c[node*8 + c*2 + r];
        float m = fmaxf(fmaxf(v[0], v[1]), fmaxf(v[2], v[3]));
        float e[4], sum = 0.f;
#pragma unroll
        for (int c = 0; c < 4; c++) { e[c] = expf(v[c] - m); sum += e[c]; }
        float inv = 1.f / sum;
#pragma unroll
        for (int c = 0; c < 4; c++) {
            float nv = e[c] * inv;
            nm_sm[(r*4 + c)*256 + node] = nv;
            g_nm[(size_t)(r*4 + c)*NN + gb + node] = nv;
        }
    }
    __syncthreads();

    float wp[20];
    {
        const int e = tid;
        int s = ei[ge + e] - gb;
        int d = ei[NE + ge + e] - gb;
        sl[e] = s; dl[e] = d;
        atomicAdd(&deg[d], 1);
        atomicAdd(&deg_s[s], 1);
        const float4* earow = (const float4*)(edge_attr + (size_t)(ge + e)*16);
        float4 e0 = earow[0], e1 = earow[1], e2 = earow[2], e3 = earow[3];

        float ns[8], nd[8];
#pragma unroll
        for (int rc = 0; rc < 8; rc++) {
            ns[rc] = nm_sm[rc*256 + s];
            nd[rc] = nm_sm[rc*256 + d];
        }
        __syncthreads();
        float4* eadst = (float4*)(ea_sm + e*16);
        eadst[0] = e0; eadst[1] = e1; eadst[2] = e2; eadst[3] = e3;
#pragma unroll
        for (int rc = 0; rc < 8; rc++)
            wnum_c[e*8 + rc] = nd[rc]*nd[rc]*ns[rc];
#pragma unroll
        for (int r = 0; r < 2; r++) {
            int b = r*4, w0 = r*10;
            wp[w0+0] = ns[b+0]*nd[b+1];
            wp[w0+1] = ns[b+0]*nd[b+2];
            wp[w0+2] = ns[b+0]*nd[b+3];
            wp[w0+3] = ns[b+1]*nd[b+2];
            wp[w0+4] = ns[b+1]*nd[b+3];
            wp[w0+5] = ns[b+2]*nd[b+3];
#pragma unroll
            for (int c = 0; c < 4; c++) wp[w0+6+c] = ns[b+c]*nd[b+c];
        }
    }
#pragma unroll
    for (int p = 0; p < 20; p++)
        for (int o = 16; o > 0; o >>= 1)
            wp[p] += __shfl_down_sync(0xffffffffu, wp[p], o);
    if ((tid & 31) == 0)
#pragma unroll
        for (int p = 0; p < 20; p++) atomicAdd(&w_sm[p], wp[p]);
    __syncthreads();

    {
        const int eh = tid >> 7, rcb = (tid >> 4) & 7, qb = tid & 15;
        float nacc = 0.f;
        for (int el = eh*128; el < eh*128 + 128; el++)
            nacc = fmaf(wnum_c[el*8 + rcb], ea_sm[el*16 + qb], nacc);
        red_sm[tid] = nacc;
    }
    __syncthreads();
    if (tid < 256) {
        int rc = tid >> 5, lane = tid & 31;
        float s = 0.f;
        for (int n = lane; n < PN; n += 32) s += nm_sm[rc*256 + n];
        for (int o = 16; o > 0; o >>= 1) s += __shfl_down_sync(0xffffffffu, s, o);
        if (lane == 0) { denr_sm[rc] = s; den_sm[rc] = s + 1e-6f; }
    }
    if (tid >= 512 && tid < 640) {
        int t = tid - 512;
        float v = 0.f;
#pragma unroll
        for (int j = 0; j < 8; j++) v += red_sm[t + j*128];
        numea_sm[t] = v;
    }

    if (tid < 64) {
        int lane = tid & 31;
        int* dga = (tid < 32) ? deg : deg_s;
        int* ofa = (tid < 32) ? off : off_s;
        int run = 0;
        for (int seg = 0; seg < 8; seg++) {
            int dv = dga[seg*32 + lane];
            int v = dv;
#pragma unroll
            for (int o = 1; o < 32; o <<= 1) {
                int t = __shfl_up_sync(0xffffffffu, v, o);
                if (lane >= o) v += t;
            }
            ofa[seg*32 + lane] = run + v - dv;
            run += __shfl_sync(0xffffffffu, v, 31);
        }
        if (lane == 31) ofa[PN] = run;
    }
    __syncthreads();
    if (tid < PN) { cur[tid] = off[tid]; cur_s[tid] = off_s[tid]; }
    __syncthreads();
    {
        int pos = atomicAdd(&cur[dl[tid]], 1);
        csr[pos] = tid;
        int pos2 = atomicAdd(&cur_s[sl[tid]], 1);
        csr_s[pos2] = tid;
    }
    __syncthreads();

    if (tid < PN) g_deg[gb + tid] = (float)deg[tid];

    for (int i = tid; i < PN*8; i += 1024) {
        int s = i >> 3, rc = i & 7;
        float a = 0.f;
        int e0 = off_s[s], e1 = off_s[s + 1];
        for (int ii = e0; ii < e1; ii++)
            a += wnum_c[csr_s[ii]*8 + rc];
        srcw[rc*256 + s] = a;
    }

    for (int i = tid; i < PN*16; i += 1024) {
        int nl = i >> 4, q = i & 15;
        float a = 0.f;
        int e0 = off[nl], e1 = off[nl + 1];
        for (int ii = e0; ii < e1; ii++)
            a += ea_sm[csr[ii]*16 + q];
        g_aggea[(size_t)(gb + nl)*16 + q] = a;
    }
    __syncthreads();

    {
        const int d64 = tid & 63, grp = tid >> 6;
        float bl[8];
#pragma unroll
        for (int rc = 0; rc < 8; rc++) bl[rc] = 0.f;
        for (int nl = grp; nl < PN; nl += 16) {
            float xv = xf[(size_t)(gb + nl)*64 + d64];
#pragma unroll
            for (int rc = 0; rc < 8; rc++)
                bl[rc] = fmaf(nm_sm[rc*256 + nl], xv, bl[rc]);
            float a = 0.f;
            int e0 = off[nl], e1 = off[nl + 1];
            for (int ii = e0; ii < e1; ii++)
                a += xf[(size_t)(gb + sl[csr[ii]])*64 + d64];
            g_aggxf[(size_t)(gb + nl)*64 + d64] = a;
        }
#pragma unroll
        for (int rc = 0; rc < 8; rc++)
            ea_sm[grp*512 + rc*64 + d64] = bl[rc];
    }
    __syncthreads();
    if (tid < 512) {
        float s = 0.f;
#pragma unroll
        for (int j = 0; j < 16; j++) s += ea_sm[j*512 + tid];
        int rc = tid >> 6, q = tid & 63;
        int r = rc >> 2, ci = rc & 3;
        g_bcxf[((size_t)(r*NG + g)*4 + ci)*64 + q] = s;
    }
    if (tid < 8) {
        int r = tid >> 2, ci = tid & 3;
        g_denr[(size_t)(r*NG + g)*4 + ci] = denr_sm[tid];
    }
    __syncthreads();

    {
        const int d = tid & 127, grp8 = tid >> 7;
        float numa[8];
#pragma unroll
        for (int rc = 0; rc < 8; rc++) numa[rc] = 0.f;
        for (int nl = grp8; nl < PN; nl += 8) {
            float hv = g_h[(size_t)(gb + nl)*128 + d];
#pragma unroll
            for (int rc = 0; rc < 8; rc++)
                numa[rc] = fmaf(nm_sm[rc*256 + nl] + srcw[rc*256 + nl], hv, numa[rc]);
        }
#pragma unroll
        for (int rc = 0; rc < 8; rc++)
            ea_sm[grp8*1024 + rc*128 + d] = numa[rc];
    }
    __syncthreads();
    {
        float s = 0.f;
#pragma unroll
        for (int j = 0; j < 8; j++) s += ea_sm[j*1024 + tid];
        numh_sm[tid] = s;
    }
    __syncthreads();

    {
        const int rc = tid >> 7, dd = tid & 127;
        const int r = rc >> 2, ci = rc & 3;
        for (int i = tid; i < 2048; i += 1024) We_sm[i] = Wedge[i];
        __syncthreads();
        float v = numh_sm[rc*128 + dd];
#pragma unroll
        for (int q = 0; q < 16; q++)
            v = fmaf(numea_sm[rc*16 + q], We_sm[q*128 + dd], v);
        v /= den_sm[rc];
        cx_sm[rc*128 + dd] = v;
        g_cx[((size_t)(r*NG + g)*4 + ci)*128 + dd] = v;
        __syncthreads();
        const int pidx[4][4] = { {6,0,1,2}, {0,7,3,4}, {1,3,8,5}, {2,4,5,9} };
        float a = 0.f;
#pragma unroll
        for (int j = 0; j < 4; j++) {
            float w = w_sm[r*10 + pidx[ci][j]];
            if (ci == j) w *= 0.5f;
            a = fmaf(w, cx_sm[(r*4 + j)*128 + dd], a);
        }
        g_ccraw[((size_t)(r*NG + g)*4 + ci)*128 + dd] = a;
    }

    if (tid < 32) {
        const int pidx[4][4] = { {6,0,1,2}, {0,7,3,4}, {1,3,8,5}, {2,4,5,9} };
        int r = tid >> 4, idx = tid & 15;
        int i = idx >> 2, j = idx & 3;
        float v = w_sm[r*10 + pidx[i][j]];
        if (i == j) v *= 0.5f;
        float m = v;
        for (int o = 16; o > 0; o >>= 1)
            m = fmaxf(m, __shfl_down_sync(0xffffffffu, m, o));
        if (tid == 0) atomicMax(&g_maxbits, __float_as_uint(m));
    }
}

// ---------------------------------------------------------------------------
// Final fused: hcw = relu(hp0+hp1+hp2)@Wcb (in-block, per graph);
// node = mean_r relu(Z + Sum_c nm*hcw); pool; heads.  grid = NG, 1024 thr.
// ---------------------------------------------------------------------------
__global__ void __launch_bounds__(1024)
final_kernel(const float* __restrict__ Wcb,
             const float* __restrict__ W_inter,
             const float* __restrict__ b_inter,
             const float* __restrict__ W_out,
             const float* __restrict__ b_out,
             float* __restrict__ out) {
    extern __shared__ float sm[];
    float* Wcb_s = sm;             // 16384
    float* hc    = Wcb_s + 16384;  // 1024
    float* hcw   = hc + 1024;      // 1024
    float* nm_s  = hcw + 1024;     // 2048
    float* red   = nm_s + 2048;    // 1024
    float* gs    = red + 1024;     // 128
    float* emb   = gs + 128;       // 128

    int g = blockIdx.x, tid = threadIdx.x;

    for (int i = tid*4; i < 16384; i += 4096)
        *(float4*)(Wcb_s + i) = *(const float4*)(Wcb + i);
    {
        int rc = tid >> 7, k = tid & 127;
        int r = rc >> 2, c = rc & 3;
        size_t o = ((size_t)(r*NG + g)*4 + c)*128 + k;
        float v = g_hp[o] + g_hp[131072 + o] + g_hp[262144 + o];
        hc[tid] = fmaxf(v, 0.f);
    }
    for (int i = tid; i < 2048; i += 1024)
        nm_s[i] = g_nm[(size_t)(i >> 8)*NN + g*PN + (i & 255)];
    __syncthreads();

    {
        int rc = tid >> 7, d = tid & 127;
        float a = 0.f;
#pragma unroll 4
        for (int k = 0; k < 128; k++)
            a = fmaf(hc[rc*128 + k], Wcb_s[k*128 + d], a);
        hcw[tid] = a;
    }
    __syncthreads();

    int d = tid & 127, q8 = tid >> 7;
    float acc = 0.f;
#pragma unroll 8
    for (int nl = q8; nl < PN; nl += 8) {
        float z = g_Z[(size_t)(g*PN + nl)*128 + d];
        float y0 = 0.f, y1 = 0.f;
#pragma unroll
        for (int c = 0; c < 4; c++) {
            y0 = fmaf(nm_s[c*256 + nl],       hcw[c*128 + d],       y0);
            y1 = fmaf(nm_s[(4 + c)*256 + nl], hcw[512 + c*128 + d], y1);
        }
        acc += 0.5f * (fmaxf(z + y0, 0.f) + fmaxf(z + y1, 0.f));
    }
    red[tid] = acc;
    __syncthreads();
    if (tid < 128) {
        float s = 0.f;
#pragma unroll
        for (int j = 0; j < 8; j++) s += red[tid + j*128];
        gs[tid] = s * (1.0f / PN);
    }
    __syncthreads();
    if (tid < 128) {
        float e = b_inter[tid];
        for (int k = 0; k < 128; k++) e = fmaf(gs[k], W_inter[k*128 + tid], e);
        emb[tid] = e;
    }
    __syncthreads();
    if (tid < OUTD) {
        float o = b_out[tid];
        for (int k = 0; k < 128; k++) o = fmaf(emb[k], W_out[k*OUTD + tid], o);
        out[g*OUTD + tid] = o;
    }
}

// ---------------------------------------------------------------------------
extern "C" void kernel_launch(void* const* d_in, const int* in_sizes, int n_in,
                              void* d_out, int out_size) {
    const float* x_feat    = (const float*)d_in[0];
    const float* edge_attr = (const float*)d_in[1];
    const float* W_atom    = (const float*)d_in[2];
    const float* b_atom    = (const float*)d_in[3];
    const float* W_score   = (const float*)d_in[4];
    const float* W_edge    = (const float*)d_in[5];
    const float* W_b2c     = (const float*)d_in[6];
    const float* W_bb      = (const float*)d_in[7];
    const float* W_bc      = (const float*)d_in[8];
    const float* W_cb      = (const float*)d_in[9];
    const float* W_cc      = (const float*)d_in[10];
    const float* W_sb      = (const float*)d_in[11];
    const float* W_sc      = (const float*)d_in[12];
    const float* W_inter   = (const float*)d_in[13];
    const float* b_inter   = (const float*)d_in[14];
    const float* W_out     = (const float*)d_in[15];
    const float* b_out     = (const float*)d_in[16];
    const int*   edge_index= (const int*)d_in[17];
    float* out = (float*)d_out;

    cudaFuncSetAttribute(mega1, cudaFuncAttributeMaxDynamicSharedMemorySize, 70000);
    cudaFuncSetAttribute(mega2, cudaFuncAttributeMaxDynamicSharedMemorySize, 110000);
    cudaFuncSetAttribute(graph_kernel, cudaFuncAttributeMaxDynamicSharedMemorySize, 152000);
    cudaFuncSetAttribute(final_kernel, cudaFuncAttributeMaxDynamicSharedMemorySize, 90000);

    const size_t smA = 2*ASTRIDE*8;   // double-buffered packed A tile = 34816

    // 1. fused weights + counter reset
    prep_big<<<277, 128>>>(W_atom, b_atom, W_b2c, W_sb, W_bb, W_edge, W_bc, W_score);
    // 2. h-GEMM (single wave)
    mega1<<<256, 256, 64*512 + smA>>>(x_feat);
    // 3. per-graph fused pass (nm, CSRs, srcw, aggea/aggxf, bcxf, numh, cx, ccraw)
    graph_kernel<<<NG, 1024, 148200>>>(x_feat, edge_attr, edge_index, W_edge);
    // 4. Z-GEMM (K=144) + hcent partials in one launch (280 blocks, one wave)
    mega2<<<280, 256, (64+64+16)*512 + smA>>>(x_feat, W_cc, W_sc);
    // 5. fused hcw + Y + relu + mean + pool + heads
    final_kernel<<<NG, 1024, 88000>>>(W_cb, W_inter, b_inter, W_out, b_out, out);
}

// round 17
// speedup vs baseline: 1.0910x; 1.0165x over previous
#include <cuda_runtime.h>
#include <math.h>

#define NG   128
#define PN   256
#define EPG  1024
#define NN   (NG*PN)     // 32768
#define NE   (NG*EPG)    // 131072
#define DD   128
#define OUTD 10

// ---------------- device scratch ----------------
__device__ float g_h[NN*DD];
__device__ unsigned int g_hflag[NG];
__device__ float g_nm[8*NN];              // [(r*4+c)*NN + n]
__device__ float g_aggxf[NN*64];
__device__ float g_deg[NN];
__device__ float g_aggea[NN*16];
__device__ float g_bcxf[2*NG*4*64];       // 1024 x 64:  sum_n nm * xf
__device__ float g_denr[2*NG*4];          // raw nm sums (no eps)
__device__ float g_cx[2*NG*4*DD];         // cent_x, 1024 x 128
__device__ float g_ccraw[2*NG*4*DD];      // Wgraw @ cent_x (unnormalized)
__device__ float g_hp[3*2*NG*4*DD];       // hcent partials (3 x 1024 x 128)
__device__ unsigned int g_maxbits;
__device__ float g_Z[NN*DD];
// fused weights
__device__ float g_Wab[64*128];           // Wa@W_b2c
__device__ float g_Wasb[64*128];          // Wa@W_sb
__device__ float g_Wawbb[64*128];         // Wa@W_bb
__device__ float g_WaWbc[64*128];         // Wa@W_bc
__device__ float g_W3[16*128];            // We@W_bb
__device__ float g_biash[128];            // ba@W_b2c
__device__ float g_biasz[128];            // ba@W_sb
__device__ float g_babb[128];             // ba@W_bb
__device__ float g_baWbc[128];            // ba@W_bc
__device__ float g_Was[64*8];             // Wa@W_score
__device__ float g_bs[8];                 // ba@W_score

// ---------------- packed f32x2 helpers ----------------
typedef unsigned long long u64t;
__device__ __forceinline__ u64t pk2(float lo, float hi) {
    u64t r; asm("mov.b64 %0, {%1,%2};" : "=l"(r) : "f"(lo), "f"(hi)); return r;
}
__device__ __forceinline__ void upk2(u64t v, float& lo, float& hi) {
    asm("mov.b64 {%0,%1}, %2;" : "=f"(lo), "=f"(hi) : "l"(v));
}
__device__ __forceinline__ void fma2(u64t& d, u64t a, u64t b) {
    asm("fma.rn.f32x2 %0, %1, %2, %0;" : "+l"(d) : "l"(a), "l"(b));
}

// ---------------------------------------------------------------------------
// GEMM pass (R14): 128 rows x 128 cols per block, 256 threads.
// ---------------------------------------------------------------------------
template<bool SC>
__device__ __forceinline__ void mma_pass2(const float* __restrict__ A, int K,
                                          const float* __restrict__ Ws,
                                          u64t* As, int row0, int tid,
                                          int tr, int tc2, u64t acc[8][4],
                                          float ascale) {
    float4 pre[2];
#pragma unroll
    for (int it = 0; it < 2; it++) {
        int idx = tid + it*256; int lr = idx >> 2, lc = (idx & 3) * 4;
        pre[it] = *(const float4*)(A + (size_t)(row0 + lr)*K + lc);
    }
    for (int k0 = 0; k0 < K; k0 += 16) {
        __syncthreads();
#pragma unroll
        for (int it = 0; it < 2; it++) {
            int idx = tid + it*256; int lr = idx >> 2, lc = (idx & 3) * 4;
            float4 v = pre[it];
            if (SC) { v.x *= ascale; v.y *= ascale; v.z *= ascale; v.w *= ascale; }
            As[lr*17 + lc + 0] = pk2(v.x, v.x);
            As[lr*17 + lc + 1] = pk2(v.y, v.y);
            As[lr*17 + lc + 2] = pk2(v.z, v.z);
            As[lr*17 + lc + 3] = pk2(v.w, v.w);
        }
        __syncthreads();
        if (k0 + 16 < K) {
#pragma unroll
            for (int it = 0; it < 2; it++) {
                int idx = tid + it*256; int lr = idx >> 2, lc = (idx & 3) * 4;
                pre[it] = *(const float4*)(A + (size_t)(row0 + lr)*K + k0 + 16 + lc);
            }
        }
#pragma unroll
        for (int kk = 0; kk < 16; kk++) {
            const float* wrow = Ws + (k0 + kk)*128;
            u64t wv[4];
#pragma unroll
            for (int jp = 0; jp < 4; jp++)
                wv[jp] = *(const u64t*)(wrow + tc2 + 32*jp);
            u64t ap[8];
#pragma unroll
            for (int i = 0; i < 8; i++)
                ap[i] = As[(tr + 16*i)*17 + kk];
#pragma unroll
            for (int i = 0; i < 8; i++)
#pragma unroll
                for (int jp = 0; jp < 4; jp++) fma2(acc[i][jp], ap[i], wv[jp]);
        }
    }
}

__device__ __forceinline__ void acc_store(u64t acc[8][4], float* __restrict__ out,
                                          int row0, int tr, int tc2, int relu_flag) {
#pragma unroll
    for (int i = 0; i < 8; i++) {
        int row = row0 + tr + 16*i;
#pragma unroll
        for (int jp = 0; jp < 4; jp++) {
            int cb = tc2 + 32*jp;
            float lo, hi; upk2(acc[i][jp], lo, hi);
            if (relu_flag) { lo = fmaxf(lo, 0.f); hi = fmaxf(hi, 0.f); }
            out[(size_t)row*128 + cb]     = lo;
            out[(size_t)row*128 + cb + 1] = hi;
        }
    }
}

__device__ __forceinline__ void gemm_body(
        const float* __restrict__ A1, const float* __restrict__ W1, int K1,
        const float* __restrict__ A2, const float* __restrict__ W2, int K2,
        const float* __restrict__ A3, const float* __restrict__ W3, int K3,
        const float* __restrict__ bias,
        const float* __restrict__ rowscale,
        const float* __restrict__ rowvec,
        int relu_flag, float* __restrict__ out,
        int blk, float* sm) {
    float* Ws1 = sm;
    float* Ws2 = Ws1 + K1*128;
    float* Ws3 = Ws2 + K2*128;
    u64t*  As  = (u64t*)(Ws3 + K3*128);

    const int tid = threadIdx.x;
    const int tr = tid >> 4, tc2 = (tid & 15) * 2;
    const int row0 = blk * 128;

    for (int i = tid*4; i < K1*128; i += 1024) *(float4*)(Ws1+i) = *(const float4*)(W1+i);
    if (A2) for (int i = tid*4; i < K2*128; i += 1024) *(float4*)(Ws2+i) = *(const float4*)(W2+i);
    if (A3) for (int i = tid*4; i < K3*128; i += 1024) *(float4*)(Ws3+i) = *(const float4*)(W3+i);

    u64t acc[8][4];
#pragma unroll
    for (int i = 0; i < 8; i++)
#pragma unroll
        for (int j = 0; j < 4; j++) acc[i][j] = 0ull;

    mma_pass2<false>(A1, K1, Ws1, As, row0, tid, tr, tc2, acc, 1.f);
    if (A2) mma_pass2<false>(A2, K2, Ws2, As, row0, tid, tr, tc2, acc, 1.f);
    if (A3) mma_pass2<false>(A3, K3, Ws3, As, row0, tid, tr, tc2, acc, 1.f);

#pragma unroll
    for (int i = 0; i < 8; i++) {
        int row = row0 + tr + 16*i;
        float rs = rowscale ? rowscale[row] : 0.f;
#pragma unroll
        for (int jp = 0; jp < 4; jp++) {
            int cb = tc2 + 32*jp;
            float lo, hi; upk2(acc[i][jp], lo, hi);
            if (bias)   { lo += bias[cb];        hi += bias[cb+1]; }
            if (rowvec) { lo += rs * rowvec[cb]; hi += rs * rowvec[cb+1]; }
            if (relu_flag) { lo = fmaxf(lo, 0.f); hi = fmaxf(hi, 0.f); }
            out[(size_t)row*128 + cb]     = lo;
            out[(size_t)row*128 + cb + 1] = hi;
        }
    }
}

// ---------------------------------------------------------------------------
// MEGA2: blocks 0-255 Z-GEMM (K=144);
// blocks 256-279: hcent partial GEMMs (hb = t&7, p = t>>3).
// ---------------------------------------------------------------------------
__global__ void __launch_bounds__(256, 2)
mega2(const float* __restrict__ x_feat,
      const float* __restrict__ Wcc_, const float* __restrict__ Wsc) {
    extern __shared__ float sm[];
    int b = blockIdx.x;
    if (b < 256) {
        gemm_body(g_aggxf, g_Wawbb, 64, x_feat, g_Wasb, 64, g_aggea, g_W3, 16,
                  g_biasz, g_deg, g_babb, 0, g_Z, b, sm);
        return;
    }
    const int t = b - 256;                 // 0..23
    const int hb = t & 7, p = t >> 3;
    const int tid = threadIdx.x;
    const int tr = tid >> 4, tc2 = (tid & 15) * 2;

    if (p == 0) {
        gemm_body(g_bcxf, g_WaWbc, 64, nullptr, nullptr, 0, nullptr, nullptr, 0,
                  nullptr, g_denr, g_baWbc, 0, g_hp, hb, sm);
    } else {
        float* Ws = sm;
        u64t*  As = (u64t*)(sm + 128*128);
        const int row0 = hb * 128;
        const float* Wsel = (p == 1) ? Wcc_ : Wsc;
        const float* Asel = (p == 1) ? g_ccraw : g_cx;
        const float ascale = (p == 1)
            ? 1.f / (__uint_as_float(g_maxbits) + 1e-9f) : 1.f;
        for (int i = tid*4; i < 128*128; i += 1024)
            *(float4*)(Ws+i) = *(const float4*)(Wsel+i);
        u64t acc[8][4];
#pragma unroll
        for (int i = 0; i < 8; i++)
#pragma unroll
            for (int j = 0; j < 4; j++) acc[i][j] = 0ull;
        mma_pass2<true>(Asel, 128, Ws, As, row0, tid, tr, tc2, acc, ascale);
        acc_store(acc, g_hp + (size_t)p*131072, row0, tr, tc2, 0);
    }
}

// ---------------------------------------------------------------------------
// Parallel weight precompute + counters reset.  grid = 277 x 128.
// ---------------------------------------------------------------------------
__global__ void prep_big(const float* __restrict__ Wa, const float* __restrict__ ba,
                         const float* __restrict__ Wb2c, const float* __restrict__ Wsb,
                         const float* __restrict__ Wbb, const float* __restrict__ We,
                         const float* __restrict__ Wbc, const float* __restrict__ Wscore) {
    int b = blockIdx.x, d = threadIdx.x;
    if (b < NG && d == 0) g_hflag[b] = 0u;
    if (b < 64) {
        float a = 0.f;
        for (int k = 0; k < 128; k++) a = fmaf(Wa[b*128+k], Wb2c[k*128+d], a);
        g_Wab[b*128+d] = a;
    } else if (b < 128) {
        int f = b - 64; float a = 0.f;
        for (int k = 0; k < 128; k++) a = fmaf(Wa[f*128+k], Wsb[k*128+d], a);
        g_Wasb[f*128+d] = a;
    } else if (b < 144) {
        int q = b - 128; float a = 0.f;
        for (int k = 0; k < 128; k++) a = fmaf(We[q*128+k], Wbb[k*128+d], a);
        g_W3[q*128+d] = a;
    } else if (b < 208) {
        int f = b - 144; float a = 0.f;
        for (int k = 0; k < 128; k++) a = fmaf(Wa[f*128+k], Wbb[k*128+d], a);
        g_Wawbb[f*128+d] = a;
    } else if (b < 272) {
        int f = b - 208; float a = 0.f;
        for (int k = 0; k < 128; k++) a = fmaf(Wa[f*128+k], Wbc[k*128+d], a);
        g_WaWbc[f*128+d] = a;
    } else if (b == 272) {
        float a = 0.f;
        for (int k = 0; k < 128; k++) a = fmaf(ba[k], Wb2c[k*128+d], a);
        g_biash[d] = a;
    } else if (b == 273) {
        float a = 0.f;
        for (int k = 0; k < 128; k++) a = fmaf(ba[k], Wsb[k*128+d], a);
        g_biasz[d] = a;
    } else if (b == 274) {
        float a = 0.f;
        for (int k = 0; k < 128; k++) a = fmaf(ba[k], Wbb[k*128+d], a);
        g_babb[d] = a;
        if (d == 0) g_maxbits = 0u;
    } else if (b == 275) {
        float a = 0.f;
        for (int k = 0; k < 128; k++) a = fmaf(ba[k], Wbc[k*128+d], a);
        g_baWbc[d] = a;
    } else {
        for (int o = d; o < 520; o += 128) {
            int r = o >> 3, q = o & 7;
            const float* L = (r < 64) ? (Wa + r*128) : ba;
            float a = 0.f;
            for (int k = 0; k < 128; k++) a = fmaf(L[k], Wscore[k*8+q], a);
            if (r < 64) g_Was[r*8+q] = a; else g_bs[q] = a;
        }
    }
}

// ---------------------------------------------------------------------------
// GKERN: 256 blocks x 1024 threads.
//  blocks 0-127:   h-GEMM for graph b: g_h[gb..gb+255] = relu(xf@Wab + biash)
//                  then set g_hflag[b].  (1024-thr tile: 256 rows x 128 cols)
//  blocks 128-255: per-graph fused pass for graph b-128; spins on g_hflag
//                  just before the numh phase (h-blocks dispatch first, so
//                  the spin virtually never engages).
// ---------------------------------------------------------------------------
__global__ void __launch_bounds__(1024)
gkern(const float* __restrict__ xf,
      const float* __restrict__ edge_attr,
      const int* __restrict__ ei,
      const float* __restrict__ Wedge) {
    extern __shared__ float smf[];
    const int tid = threadIdx.x;

    if (blockIdx.x < NG) {
        // ================= h-GEMM block =================
        const int g = blockIdx.x;
        float* Ws = smf;                   // 8192 floats
        u64t*  As = (u64t*)(smf + 8192);   // 256*17 u64
        const int tr = tid >> 4;           // 0..63 -> rows {tr,+64,+128,+192}
        const int tc2 = (tid & 15) * 2;
        const int row0 = g * PN;
        const int lr = tid >> 2, lc = (tid & 3) * 4;

        for (int i = tid*4; i < 8192; i += 4096)
            *(float4*)(Ws+i) = *(const float4*)(g_Wab+i);

        u64t acc[4][4];
#pragma unroll
        for (int i = 0; i < 4; i++)
#pragma unroll
            for (int j = 0; j < 4; j++) acc[i][j] = 0ull;

        for (int k0 = 0; k0 < 64; k0 += 16) {
            __syncthreads();
            float4 v = *(const float4*)(xf + (size_t)(row0 + lr)*64 + k0 + lc);
            As[lr*17 + lc + 0] = pk2(v.x, v.x);
            As[lr*17 + lc + 1] = pk2(v.y, v.y);
            As[lr*17 + lc + 2] = pk2(v.z, v.z);
            As[lr*17 + lc + 3] = pk2(v.w, v.w);
            __syncthreads();
#pragma unroll
            for (int kk = 0; kk < 16; kk++) {
                const float* wrow = Ws + (k0 + kk)*128;
                u64t wv[4];
#pragma unroll
                for (int jp = 0; jp < 4; jp++)
                    wv[jp] = *(const u64t*)(wrow + tc2 + 32*jp);
                u64t ap[4];
#pragma unroll
                for (int i = 0; i < 4; i++)
                    ap[i] = As[(tr + 64*i)*17 + kk];
#pragma unroll
                for (int i = 0; i < 4; i++)
#pragma unroll
                    for (int jp = 0; jp < 4; jp++) fma2(acc[i][jp], ap[i], wv[jp]);
            }
        }
#pragma unroll
        for (int i = 0; i < 4; i++) {
            int row = row0 + tr + 64*i;
#pragma unroll
            for (int jp = 0; jp < 4; jp++) {
                int cb = tc2 + 32*jp;
                float lo, hi; upk2(acc[i][jp], lo, hi);
                lo = fmaxf(lo + g_biash[cb], 0.f);
                hi = fmaxf(hi + g_biash[cb+1], 0.f);
                g_h[(size_t)row*128 + cb]     = lo;
                g_h[(size_t)row*128 + cb + 1] = hi;
            }
        }
        __threadfence();
        __syncthreads();
        if (tid == 0) atomicExch(&g_hflag[g], 1u);
        return;
    }

    // ================= graph block (R14 body) =================
    float* nm_sm    = smf;               // 2048
    float* srcw     = nm_sm + 2048;      // 2048
    float* ea_sm    = srcw + 2048;       // 16384
    float* wnum_c   = ea_sm + 16384;     // 8192
    float* numh_sm  = wnum_c + 8192;     // 1024
    float* red_sm   = numh_sm + 1024;    // 1024
    float* numea_sm = red_sm + 1024;     // 128
    float* was_sm   = numea_sm + 128;    // 520
    float* w_sm     = was_sm + 520;      // 24
    float* den_sm   = w_sm + 24;         // 8
    float* denr_sm  = den_sm + 8;        // 8
    int* sl    = (int*)(denr_sm + 8);    // 1024
    int* dl    = sl + 1024;              // 1024
    int* deg   = dl + 1024;              // 256
    int* off   = deg + 256;              // 257
    int* cur   = off + 257;              // 256
    int* csr   = cur + 256;              // 1024
    int* deg_s = csr + 1024;             // 256
    int* off_s = deg_s + 256;            // 257
    int* cur_s = off_s + 257;            // 256
    int* csr_s = cur_s + 256;            // 1024

    float* cx_sm = ea_sm;
    float* We_sm = wnum_c;

    const int g = blockIdx.x - NG;
    const int gb = g * PN;
    const int ge = g * EPG;

    for (int i = tid*4; i < PN*64; i += 4096)
        *(float4*)(ea_sm + i) = *(const float4*)(xf + (size_t)gb*64 + i);
    for (int i = tid; i < 512; i += 1024) was_sm[i] = g_Was[i];
    if (tid < 8) was_sm[512 + tid] = g_bs[tid];
    if (tid < PN) { deg[tid] = 0; deg_s[tid] = 0; }
    if (tid < 20) w_sm[tid] = 0.f;
    __syncthreads();
    {
        int node = tid >> 2, q = tid & 3;
        float s0 = was_sm[512 + q], s1 = was_sm[512 + q + 4];
        const float* xrow = ea_sm + node*64;
        for (int k = 0; k < 64; k++) {
            float a = xrow[k];
            s0 = fmaf(a, was_sm[k*8 + q], s0);
            s1 = fmaf(a, was_sm[k*8 + q + 4], s1);
        }
        wnum_c[node*8 + q]     = s0;
        wnum_c[node*8 + q + 4] = s1;
    }
    __syncthreads();
    if (tid < 512) {
        int node = tid >> 1, r = tid & 1;
        float v[4];
#pragma unroll
        for (int c = 0; c < 4; c++) v[c] = wnum_c[node*8 + c*2 + r];
        float m = fmaxf(fmaxf(v[0], v[1]), fmaxf(v[2], v[3]));
        float e[4], sum = 0.f;
#pragma unroll
        for (int c = 0; c < 4; c++) { e[c] = expf(v[c] - m); sum += e[c]; }
        float inv = 1.f / sum;
#pragma unroll
        for (int c = 0; c < 4; c++) {
            float nv = e[c] * inv;
            nm_sm[(r*4 + c)*256 + node] = nv;
            g_nm[(size_t)(r*4 + c)*NN + gb + node] = nv;
        }
    }
    __syncthreads();

    float wp[20];
    {
        const int e = tid;
        int s = ei[ge + e] - gb;
        int d = ei[NE + ge + e] - gb;
        sl[e] = s; dl[e] = d;
        atomicAdd(&deg[d], 1);
        atomicAdd(&deg_s[s], 1);
        const float4* earow = (const float4*)(edge_attr + (size_t)(ge + e)*16);
        float4 e0 = earow[0], e1 = earow[1], e2 = earow[2], e3 = earow[3];

        float ns[8], nd[8];
#pragma unroll
        for (int rc = 0; rc < 8; rc++) {
            ns[rc] = nm_sm[rc*256 + s];
            nd[rc] = nm_sm[rc*256 + d];
        }
        __syncthreads();
        float4* eadst = (float4*)(ea_sm + e*16);
        eadst[0] = e0; eadst[1] = e1; eadst[2] = e2; eadst[3] = e3;
#pragma unroll
        for (int rc = 0; rc < 8; rc++)
            wnum_c[e*8 + rc] = nd[rc]*nd[rc]*ns[rc];
#pragma unroll
        for (int r = 0; r < 2; r++) {
            int b = r*4, w0 = r*10;
            wp[w0+0] = ns[b+0]*nd[b+1];
            wp[w0+1] = ns[b+0]*nd[b+2];
            wp[w0+2] = ns[b+0]*nd[b+3];
            wp[w0+3] = ns[b+1]*nd[b+2];
            wp[w0+4] = ns[b+1]*nd[b+3];
            wp[w0+5] = ns[b+2]*nd[b+3];
#pragma unroll
            for (int c = 0; c < 4; c++) wp[w0+6+c] = ns[b+c]*nd[b+c];
        }
    }
#pragma unroll
    for (int p = 0; p < 20; p++)
        for (int o = 16; o > 0; o >>= 1)
            wp[p] += __shfl_down_sync(0xffffffffu, wp[p], o);
    if ((tid & 31) == 0)
#pragma unroll
        for (int p = 0; p < 20; p++) atomicAdd(&w_sm[p], wp[p]);
    __syncthreads();

    {
        const int eh = tid >> 7, rcb = (tid >> 4) & 7, qb = tid & 15;
        float nacc = 0.f;
        for (int el = eh*128; el < eh*128 + 128; el++)
            nacc = fmaf(wnum_c[el*8 + rcb], ea_sm[el*16 + qb], nacc);
        red_sm[tid] = nacc;
    }
    __syncthreads();
    if (tid < 256) {
        int rc = tid >> 5, lane = tid & 31;
        float s = 0.f;
        for (int n = lane; n < PN; n += 32) s += nm_sm[rc*256 + n];
        for (int o = 16; o > 0; o >>= 1) s += __shfl_down_sync(0xffffffffu, s, o);
        if (lane == 0) { denr_sm[rc] = s; den_sm[rc] = s + 1e-6f; }
    }
    if (tid >= 512 && tid < 640) {
        int t = tid - 512;
        float v = 0.f;
#pragma unroll
        for (int j = 0; j < 8; j++) v += red_sm[t + j*128];
        numea_sm[t] = v;
    }

    if (tid < 64) {
        int lane = tid & 31;
        int* dga = (tid < 32) ? deg : deg_s;
        int* ofa = (tid < 32) ? off : off_s;
        int run = 0;
        for (int seg = 0; seg < 8; seg++) {
            int dv = dga[seg*32 + lane];
            int v = dv;
#pragma unroll
            for (int o = 1; o < 32; o <<= 1) {
                int t = __shfl_up_sync(0xffffffffu, v, o);
                if (lane >= o) v += t;
            }
            ofa[seg*32 + lane] = run + v - dv;
            run += __shfl_sync(0xffffffffu, v, 31);
        }
        if (lane == 31) ofa[PN] = run;
    }
    __syncthreads();
    if (tid < PN) { cur[tid] = off[tid]; cur_s[tid] = off_s[tid]; }
    __syncthreads();
    {
        int pos = atomicAdd(&cur[dl[tid]], 1);
        csr[pos] = tid;
        int pos2 = atomicAdd(&cur_s[sl[tid]], 1);
        csr_s[pos2] = tid;
    }
    __syncthreads();

    if (tid < PN) g_deg[gb + tid] = (float)deg[tid];

    for (int i = tid; i < PN*8; i += 1024) {
        int s = i >> 3, rc = i & 7;
        float a = 0.f;
        int e0 = off_s[s], e1 = off_s[s + 1];
        for (int ii = e0; ii < e1; ii++)
            a += wnum_c[csr_s[ii]*8 + rc];
        srcw[rc*256 + s] = a;
    }

    for (int i = tid; i < PN*16; i += 1024) {
        int nl = i >> 4, q = i & 15;
        float a = 0.f;
        int e0 = off[nl], e1 = off[nl + 1];
        for (int ii = e0; ii < e1; ii++)
            a += ea_sm[csr[ii]*16 + q];
        g_aggea[(size_t)(gb + nl)*16 + q] = a;
    }
    __syncthreads();

    {
        const int d64 = tid & 63, grp = tid >> 6;
        float bl[8];
#pragma unroll
        for (int rc = 0; rc < 8; rc++) bl[rc] = 0.f;
        for (int nl = grp; nl < PN; nl += 16) {
            float xv = xf[(size_t)(gb + nl)*64 + d64];
#pragma unroll
            for (int rc = 0; rc < 8; rc++)
                bl[rc] = fmaf(nm_sm[rc*256 + nl], xv, bl[rc]);
            float a = 0.f;
            int e0 = off[nl], e1 = off[nl + 1];
            for (int ii = e0; ii < e1; ii++)
                a += xf[(size_t)(gb + sl[csr[ii]])*64 + d64];
            g_aggxf[(size_t)(gb + nl)*64 + d64] = a;
        }
#pragma unroll
        for (int rc = 0; rc < 8; rc++)
            ea_sm[grp*512 + rc*64 + d64] = bl[rc];
    }
    __syncthreads();
    if (tid < 512) {
        float s = 0.f;
#pragma unroll
        for (int j = 0; j < 16; j++) s += ea_sm[j*512 + tid];
        int rc = tid >> 6, q = tid & 63;
        int r = rc >> 2, ci = rc & 3;
        g_bcxf[((size_t)(r*NG + g)*4 + ci)*64 + q] = s;
    }
    if (tid < 8) {
        int r = tid >> 2, ci = tid & 3;
        g_denr[(size_t)(r*NG + g)*4 + ci] = denr_sm[tid];
    }
    __syncthreads();

    // ---- wait for this graph's h tile (set by block g, dispatched earlier) ----
    if (tid == 0) { while (atomicAdd(&g_hflag[g], 0u) == 0u) {} }
    __syncthreads();

    {
        const int d = tid & 127, grp8 = tid >> 7;
        float numa[8];
#pragma unroll
        for (int rc = 0; rc < 8; rc++) numa[rc] = 0.f;
        for (int nl = grp8; nl < PN; nl += 8) {
            float hv = g_h[(size_t)(gb + nl)*128 + d];
#pragma unroll
            for (int rc = 0; rc < 8; rc++)
                numa[rc] = fmaf(nm_sm[rc*256 + nl] + srcw[rc*256 + nl], hv, numa[rc]);
        }
#pragma unroll
        for (int rc = 0; rc < 8; rc++)
            ea_sm[grp8*1024 + rc*128 + d] = numa[rc];
    }
    __syncthreads();
    {
        float s = 0.f;
#pragma unroll
        for (int j = 0; j < 8; j++) s += ea_sm[j*1024 + tid];
        numh_sm[tid] = s;
    }
    __syncthreads();

    {
        const int rc = tid >> 7, dd = tid & 127;
        const int r = rc >> 2, ci = rc & 3;
        for (int i = tid; i < 2048; i += 1024) We_sm[i] = Wedge[i];
        __syncthreads();
        float v = numh_sm[rc*128 + dd];
#pragma unroll
        for (int q = 0; q < 16; q++)
            v = fmaf(numea_sm[rc*16 + q], We_sm[q*128 + dd], v);
        v /= den_sm[rc];
        cx_sm[rc*128 + dd] = v;
        g_cx[((size_t)(r*NG + g)*4 + ci)*128 + dd] = v;
        __syncthreads();
        const int pidx[4][4] = { {6,0,1,2}, {0,7,3,4}, {1,3,8,5}, {2,4,5,9} };
        float a = 0.f;
#pragma unroll
        for (int j = 0; j < 4; j++) {
            float w = w_sm[r*10 + pidx[ci][j]];
            if (ci == j) w *= 0.5f;
            a = fmaf(w, cx_sm[(r*4 + j)*128 + dd], a);
        }
        g_ccraw[((size_t)(r*NG + g)*4 + ci)*128 + dd] = a;
    }

    if (tid < 32) {
        const int pidx[4][4] = { {6,0,1,2}, {0,7,3,4}, {1,3,8,5}, {2,4,5,9} };
        int r = tid >> 4, idx = tid & 15;
        int i = idx >> 2, j = idx & 3;
        float v = w_sm[r*10 + pidx[i][j]];
        if (i == j) v *= 0.5f;
        float m = v;
        for (int o = 16; o > 0; o >>= 1)
            m = fmaxf(m, __shfl_down_sync(0xffffffffu, m, o));
        if (tid == 0) atomicMax(&g_maxbits, __float_as_uint(m));
    }
}

// ---------------------------------------------------------------------------
// Final fused: hcw = relu(hp0+hp1+hp2)@Wcb (in-block, per graph);
// node = mean_r relu(Z + Sum_c nm*hcw); pool; heads.  grid = NG, 1024 thr.
// ---------------------------------------------------------------------------
__global__ void __launch_bounds__(1024)
final_kernel(const float* __restrict__ Wcb,
             const float* __restrict__ W_inter,
             const float* __restrict__ b_inter,
             const float* __restrict__ W_out,
             const float* __restrict__ b_out,
             float* __restrict__ out) {
    extern __shared__ float sm[];
    float* Wcb_s = sm;             // 16384
    float* hc    = Wcb_s + 16384;  // 1024
    float* hcw   = hc + 1024;      // 1024
    float* nm_s  = hcw + 1024;     // 2048
    float* red   = nm_s + 2048;    // 1024
    float* gs    = red + 1024;     // 128
    float* emb   = gs + 128;       // 128

    int g = blockIdx.x, tid = threadIdx.x;

    for (int i = tid*4; i < 16384; i += 4096)
        *(float4*)(Wcb_s + i) = *(const float4*)(Wcb + i);
    {
        int rc = tid >> 7, k = tid & 127;
        int r = rc >> 2, c = rc & 3;
        size_t o = ((size_t)(r*NG + g)*4 + c)*128 + k;
        float v = g_hp[o] + g_hp[131072 + o] + g_hp[262144 + o];
        hc[tid] = fmaxf(v, 0.f);
    }
    for (int i = tid; i < 2048; i += 1024)
        nm_s[i] = g_nm[(size_t)(i >> 8)*NN + g*PN + (i & 255)];
    __syncthreads();

    {
        int rc = tid >> 7, d = tid & 127;
        float a = 0.f;
#pragma unroll 4
        for (int k = 0; k < 128; k++)
            a = fmaf(hc[rc*128 + k], Wcb_s[k*128 + d], a);
        hcw[tid] = a;
    }
    __syncthreads();

    int d = tid & 127, q8 = tid >> 7;
    float acc = 0.f;
#pragma unroll 8
    for (int nl = q8; nl < PN; nl += 8) {
        float z = g_Z[(size_t)(g*PN + nl)*128 + d];
        float y0 = 0.f, y1 = 0.f;
#pragma unroll
        for (int c = 0; c < 4; c++) {
            y0 = fmaf(nm_s[c*256 + nl],       hcw[c*128 + d],       y0);
            y1 = fmaf(nm_s[(4 + c)*256 + nl], hcw[512 + c*128 + d], y1);
        }
        acc += 0.5f * (fmaxf(z + y0, 0.f) + fmaxf(z + y1, 0.f));
    }
    red[tid] = acc;
    __syncthreads();
    if (tid < 128) {
        float s = 0.f;
#pragma unroll
        for (int j = 0; j < 8; j++) s += red[tid + j*128];
        gs[tid] = s * (1.0f / PN);
    }
    __syncthreads();
    if (tid < 128) {
        float e = b_inter[tid];
        for (int k = 0; k < 128; k++) e = fmaf(gs[k], W_inter[k*128 + tid], e);
        emb[tid] = e;
    }
    __syncthreads();
    if (tid < OUTD) {
        float o = b_out[tid];
        for (int k = 0; k < 128; k++) o = fmaf(emb[k], W_out[k*OUTD + tid], o);
        out[g*OUTD + tid] = o;
    }
}

// ---------------------------------------------------------------------------
extern "C" void kernel_launch(void* const* d_in, const int* in_sizes, int n_in,
                              void* d_out, int out_size) {
    const float* x_feat    = (const float*)d_in[0];
    const float* edge_attr = (const float*)d_in[1];
    const float* W_atom    = (const float*)d_in[2];
    const float* b_atom    = (const float*)d_in[3];
    const float* W_score   = (const float*)d_in[4];
    const float* W_edge    = (const float*)d_in[5];
    const float* W_b2c     = (const float*)d_in[6];
    const float* W_bb      = (const float*)d_in[7];
    const float* W_bc      = (const float*)d_in[8];
    const float* W_cb      = (const float*)d_in[9];
    const float* W_cc      = (const float*)d_in[10];
    const float* W_sb      = (const float*)d_in[11];
    const float* W_sc      = (const float*)d_in[12];
    const float* W_inter   = (const float*)d_in[13];
    const float* b_inter   = (const float*)d_in[14];
    const float* W_out     = (const float*)d_in[15];
    const float* b_out     = (const float*)d_in[16];
    const int*   edge_index= (const int*)d_in[17];
    float* out = (float*)d_out;

    cudaFuncSetAttribute(mega2, cudaFuncAttributeMaxDynamicSharedMemorySize, 95000);
    cudaFuncSetAttribute(gkern, cudaFuncAttributeMaxDynamicSharedMemorySize, 152000);
    cudaFuncSetAttribute(final_kernel, cudaFuncAttributeMaxDynamicSharedMemorySize, 90000);

    const size_t smA = 128*17*8;   // packed u64 A tile = 17408

    // 1. fused weights + flag/counter reset
    prep_big<<<277, 128>>>(W_atom, b_atom, W_b2c, W_sb, W_bb, W_edge, W_bc, W_score);
    // 2. h-GEMM (blocks 0-127) + per-graph fused pass (blocks 128-255)
    gkern<<<2*NG, 1024, 148200>>>(x_feat, edge_attr, edge_index, W_edge);
    // 3. Z-GEMM (K=144) + hcent partials in one launch (280 blocks, one wave)
    mega2<<<280, 256, (64+64+16)*512 + smA>>>(x_feat, W_cc, W_sc);
    // 4. fused hcw + Y + relu + mean + pool + heads
    final_kernel<<<NG, 1024, 88000>>>(W_cb, W_inter, b_inter, W_out, b_out, out);
}